// round 16
// baseline (speedup 1.0000x reference)
#include <cuda_runtime.h>
#include <cuda_fp16.h>
#include <cstdint>

// Problem constants
#define BATCH 32
#define CC 2048       // channels (K of GEMM1)
#define PP 196        // H*W
#define GG 20         // decoder steps
#define DD 1024       // decode size (K of GEMM2)
#define AA 512        // att size (N of both GEMMs)

#define M1 (BATCH*PP)      // 6272 = 49*128
#define MT1 49
#define M2 (BATCH*GG)      // 640 = 5*128
#define MT2 5
#define KSEC1 64           // 2048/32 k-chunks (GEMM1)
#define KSEC2 32           // 1024/32 (GEMM2)

// GEMM tiling: CTA 128x128, 256 threads = 8 warps (2x4), warp 64x32, K=32.
#define STAGES 4
#define CHUNK_A 8192              // 128 x 32 x 2B
#define CHUNK_B 4096              // 64 x 32 x 2B (per 64-row n-tile)
#define SROW 80                   // smem row pitch (64B data + 16B pad)
#define SUBT_A (128*SROW)         // 10240
#define SUBT_B (128*SROW)         // 10240 (two stacked 64-row n-tiles)
#define STAGE_BYTES (SUBT_A + SUBT_B)    // 20480
#define SMEM_GEMM (STAGES*STAGE_BYTES)   // 81920

#define G1_BLOCKS (4*MT1)         // 196
#define G2_BLOCKS (4*MT2)         // 20

// ---------------------------------------------------------------------------
// Scratch
// ---------------------------------------------------------------------------
__device__ __align__(16) __half g_A1[MT1 * KSEC1 * 4096];   // 25.7 MB
__device__ __align__(16) __half g_B1[8   * KSEC1 * 2048];   // 2.1 MB
__device__ __align__(16) __half g_A2[MT2 * KSEC2 * 4096];
__device__ __align__(16) __half g_B2[8   * KSEC2 * 2048];
__device__ __align__(16) __half g_att_encH[M1*AA];   // (B,P,A) fp16, 6.4MB
__device__ float g_att_dec[M2*AA];                   // (B,G,A) fp32
__device__ float g_score[M2*PP];                     // (B,G,P)

// ---------------------------------------------------------------------------
__device__ __forceinline__ uint32_t smem_u32(const void* p) {
    uint32_t a;
    asm("{ .reg .u64 t; cvta.to.shared.u64 t, %1; cvt.u32.u64 %0, t; }" : "=r"(a) : "l"(p));
    return a;
}
__device__ __forceinline__ void cp16(uint32_t saddr, const void* gaddr) {
    asm volatile("cp.async.cg.shared.global [%0], [%1], 16;" :: "r"(saddr), "l"(gaddr));
}
__device__ __forceinline__ void ldm_x4(uint32_t* r, uint32_t addr) {
    asm volatile("ldmatrix.sync.aligned.m8n8.x4.shared.b16 {%0,%1,%2,%3}, [%4];"
        : "=r"(r[0]), "=r"(r[1]), "=r"(r[2]), "=r"(r[3]) : "r"(addr));
}
__device__ __forceinline__ void mma16816(float* c, const uint32_t* a, uint32_t b0, uint32_t b1) {
    asm volatile("mma.sync.aligned.m16n8k16.row.col.f32.f16.f16.f32 "
        "{%0,%1,%2,%3}, {%4,%5,%6,%7}, {%8,%9}, {%0,%1,%2,%3};"
        : "+f"(c[0]), "+f"(c[1]), "+f"(c[2]), "+f"(c[3])
        : "r"(a[0]), "r"(a[1]), "r"(a[2]), "r"(a[3]), "r"(b0), "r"(b1));
}

// ---------------------------------------------------------------------------
// Merged prep kernel.
// ---------------------------------------------------------------------------
__device__ __forceinline__ void prep_B_body(
    const float* __restrict__ W, __half* __restrict__ Bst, int kSec,
    int kc, int nb, int t, float* sm)
{
    #pragma unroll
    for (int i = 0; i < 16; i++) {
        int idx = t + i * 256;
        int kl = idx >> 7, nl = idx & 127;
        sm[kl * 129 + nl] = W[(size_t)(kc * 32 + kl) * AA + nb * 128 + nl];
    }
    __syncthreads();
    #pragma unroll
    for (int i = 0; i < 8; i++) {
        int e2 = t + i * 256;
        int row = e2 >> 4, cp = e2 & 15;
        float x0 = sm[(2*cp)   * 129 + row];
        float x1 = sm[(2*cp+1) * 129 + row];
        int nt = nb * 2 + (row >> 6);
        int rl = row & 63;
        __half2* dst = (__half2*)(Bst + ((size_t)nt * kSec + kc) * 2048);
        dst[rl * 16 + cp] = __halves2half2(__float2half_rn(x0), __float2half_rn(x1));
    }
}

__global__ __launch_bounds__(256) void k_prep_all(
    const float* __restrict__ enc, const float* __restrict__ dec,
    const float* __restrict__ W_enc, const float* __restrict__ W_dec,
    __half* __restrict__ A1, __half* __restrict__ B1,
    __half* __restrict__ A2, __half* __restrict__ B2)
{
    __shared__ float sm[32 * 129];
    const int id = blockIdx.x;
    const int t = threadIdx.x;

    if (id < 3136) {
        const int kc = id & 63, mt = id >> 6;
        #pragma unroll
        for (int i = 0; i < 16; i++) {
            int idx = t + i * 256;            // 4096 = 32c x 128m
            int cl = idx >> 7, ml = idx & 127;
            int m = mt * 128 + ml;
            int b = m / PP, p = m - b * PP;
            sm[cl * 129 + ml] = enc[((size_t)b * CC + (kc * 32 + cl)) * PP + p];
        }
        __syncthreads();
        __half2* hiC = (__half2*)(A1 + ((size_t)mt * KSEC1 + kc) * 4096);
        #pragma unroll
        for (int i = 0; i < 8; i++) {
            int e2 = t + i * 256;             // 2048 half2 = 128r x 16
            int row = e2 >> 4, cp = e2 & 15;
            float x0 = sm[(2*cp)   * 129 + row];
            float x1 = sm[(2*cp+1) * 129 + row];
            hiC[row * 16 + cp] = __halves2half2(__float2half_rn(x0), __float2half_rn(x1));
        }
    } else if (id < 3392) {
        int j = id - 3136;
        prep_B_body(W_enc, B1, KSEC1, j & 63, j >> 6, t, sm);
    } else if (id < 3520) {
        int j = id - 3392;
        prep_B_body(W_dec, B2, KSEC2, j & 31, j >> 5, t, sm);
    } else {
        int j = id - 3520;
        int kc = j & 31, mt = j >> 5;
        __half2* hiC = (__half2*)(A2 + ((size_t)mt * KSEC2 + kc) * 4096);
        #pragma unroll
        for (int i = 0; i < 8; i++) {
            int e2 = t + i * 256;
            int row = e2 >> 4, cp = e2 & 15;
            const float* src = dec + (size_t)(mt * 128 + row) * DD + kc * 32 + 2*cp;
            hiC[row * 16 + cp] = __halves2half2(__float2half_rn(src[0]), __float2half_rn(src[1]));
        }
    }
}

// ---------------------------------------------------------------------------
// Merged fp16 mma.sync GEMM. CTA 128x128, 256 threads (8 warps of 64x32),
// 4-stage pipeline, all CTAs resident (216 @ 2/SM).
// id < 196: GEMM1 -> fp16; else GEMM2 -> fp32.
// ---------------------------------------------------------------------------
__global__ __launch_bounds__(256, 2) void k_gemm_all(
    const __half* __restrict__ A1g, const __half* __restrict__ B1g,
    const __half* __restrict__ A2g, const __half* __restrict__ B2g,
    const float* __restrict__ b_enc, const float* __restrict__ b_dec,
    __half* __restrict__ out1, float* __restrict__ out2)
{
    extern __shared__ __align__(16) char smem[];
    const int id = blockIdx.x;
    const int t = threadIdx.x;
    const int lane = t & 31, wid = t >> 5;
    const int wm = wid >> 2, wn = wid & 3;        // warp tile (wm*64, wn*32)

    const bool g1 = (id < G1_BLOCKS);
    const int j  = g1 ? id : id - G1_BLOCKS;
    const int mt = j >> 2, nt = j & 3;            // nt: 128-col tile
    const int kSec = g1 ? KSEC1 : KSEC2;
    const __half* Ast = g1 ? A1g : A2g;
    const __half* Bst = g1 ? B1g : B2g;
    const float* bias = g1 ? b_enc : b_dec;

    const char* Abase  = (const char*)(Ast + (size_t)mt * kSec * 4096);
    const char* Bbase0 = (const char*)(Bst + (size_t)(nt * 2)     * kSec * 2048);
    const char* Bbase1 = (const char*)(Bst + (size_t)(nt * 2 + 1) * kSec * 2048);
    const uint32_t smem_base = smem_u32(smem);

    auto issue = [&](int kc) {
        const int s = kc % STAGES;
        const char* ga  = Abase  + (size_t)kc * CHUNK_A;
        const char* gb0 = Bbase0 + (size_t)kc * CHUNK_B;
        const char* gb1 = Bbase1 + (size_t)kc * CHUNK_B;
        const uint32_t st = smem_base + s * STAGE_BYTES;
        #pragma unroll
        for (int jj = 0; jj < 2; jj++) {   // A: 512 16B-chunks
            int u = t + jj * 256;
            cp16(st + (u >> 2) * SROW + (u & 3) * 16, ga + u * 16);
        }
        {                                   // B0: 256 chunks, B1: 256 chunks
            int u = t;
            uint32_t d = (u >> 2) * SROW + (u & 3) * 16;
            cp16(st + SUBT_A + d,            gb0 + u * 16);
            cp16(st + SUBT_A + 64*SROW + d,  gb1 + u * 16);
        }
        asm volatile("cp.async.commit_group;");
    };

    issue(0); issue(1); issue(2);

    float c[4][4][4];
    #pragma unroll
    for (int mi = 0; mi < 4; mi++)
        #pragma unroll
        for (int nj = 0; nj < 4; nj++)
            #pragma unroll
            for (int q = 0; q < 4; q++) c[mi][nj][q] = 0.f;

    for (int kc = 0; kc < kSec; kc++) {
        asm volatile("cp.async.wait_group 2;");
        __syncthreads();
        const int s = kc % STAGES;
        const uint32_t st = smem_base + s * STAGE_BYTES;
        const uint32_t aB = st + (wm * 64 + (lane & 15)) * SROW + (lane >> 4) * 16;
        const uint32_t bB = st + SUBT_A + (wn * 32 + (lane & 15)) * SROW + (lane >> 4) * 16;
        #pragma unroll
        for (int ks = 0; ks < 2; ks++) {
            const uint32_t ko = ks * 32;
            uint32_t a[4][4], bh[2][4];
            #pragma unroll
            for (int mi = 0; mi < 4; mi++) ldm_x4(a[mi], aB + mi * 16 * SROW + ko);
            #pragma unroll
            for (int nj = 0; nj < 2; nj++) ldm_x4(bh[nj], bB + nj * 16 * SROW + ko);
            #pragma unroll
            for (int mi = 0; mi < 4; mi++)
                #pragma unroll
                for (int n8 = 0; n8 < 4; n8++) {
                    const int nj = n8 >> 1, hl = n8 & 1;
                    mma16816(c[mi][n8], a[mi], bh[nj][hl], bh[nj][hl + 2]);
                }
        }
        if (kc + 3 < kSec) issue(kc + 3);
        else asm volatile("cp.async.commit_group;");
    }

    // epilogue
    const int r0b = mt * 128 + wm * 64 + (lane >> 2);
    const int ncb = nt * 128 + wn * 32 + (lane & 3) * 2;
    #pragma unroll
    for (int mi = 0; mi < 4; mi++) {
        #pragma unroll
        for (int n8 = 0; n8 < 4; n8++) {
            const int n = ncb + n8 * 8;
            const float b0 = bias[n], b1 = bias[n + 1];
            const size_t o0 = (size_t)(r0b + mi * 16) * AA + n;
            if (g1) {
                *(__half2*)(out1 + o0) =
                    __floats2half2_rn(c[mi][n8][0] + b0, c[mi][n8][1] + b1);
                *(__half2*)(out1 + o0 + 8 * AA) =
                    __floats2half2_rn(c[mi][n8][2] + b0, c[mi][n8][3] + b1);
            } else {
                float2 v0 = { c[mi][n8][0] + b0, c[mi][n8][1] + b1 };
                float2 v1 = { c[mi][n8][2] + b0, c[mi][n8][3] + b1 };
                *(float2*)(out2 + o0) = v0;
                *(float2*)(out2 + o0 + 8 * AA) = v1;
            }
        }
    }
}

// ---------------------------------------------------------------------------
// K3a: scores. Warp = 2 pixels, s[20] accumulators per lane, ONE packed
// butterfly at the end. grid (13, B).
// ---------------------------------------------------------------------------
__global__ __launch_bounds__(256) void k_score(
    const float* __restrict__ w_alpha, const float* __restrict__ b_alpha,
    float* __restrict__ score)
{
    __shared__ __half2 sdec[GG * 256];   // [g][256 half2] 20KB
    __shared__ float sw_[AA];            // 2KB
    const int b = blockIdx.y;
    const int t = threadIdx.x, warp = t >> 5, lane = t & 31;

    const float* dptr = g_att_dec + (size_t)b * GG * AA;
    for (int i = t; i < GG * 256; i += 256) {
        int g = i >> 8, c = i & 255;
        float2 d2 = *(const float2*)&dptr[g * AA + 2 * c];
        sdec[i] = __floats2half2_rn(d2.x, d2.y);
    }
    for (int i = t; i < AA; i += 256) sw_[i] = w_alpha[i];
    __syncthreads();

    const int p0 = blockIdx.x * 16 + warp * 2;
    const int p1 = p0 + 1;
    if (p0 >= PP) return;
    const bool v1 = (p1 < PP);
    const int p1c = v1 ? p1 : p0;
    const float ba = b_alpha[0];
    const __half2* ep0 = (const __half2*)(g_att_encH + ((size_t)b * PP + p0) * AA);
    const __half2* ep1 = (const __half2*)(g_att_encH + ((size_t)b * PP + p1c) * AA);

    float s0[GG], s1[GG];
    #pragma unroll
    for (int g = 0; g < GG; g++) { s0[g] = 0.f; s1[g] = 0.f; }

    #pragma unroll
    for (int i = 0; i < 8; i++) {
        float2 e0 = __half22float2(ep0[lane + 32 * i]);
        float2 e1 = __half22float2(ep1[lane + 32 * i]);
        float2 w  = *(const float2*)&sw_[2 * (lane + 32 * i)];
        #pragma unroll
        for (int g = 0; g < GG; g++) {
            float2 d = __half22float2(sdec[g * 256 + lane + 32 * i]);
            s0[g] = fmaf(fmaxf(e0.x + d.x, 0.f), w.x, s0[g]);
            s0[g] = fmaf(fmaxf(e0.y + d.y, 0.f), w.y, s0[g]);
            s1[g] = fmaf(fmaxf(e1.x + d.x, 0.f), w.x, s1[g]);
            s1[g] = fmaf(fmaxf(e1.y + d.y, 0.f), w.y, s1[g]);
        }
    }

    #pragma unroll
    for (int o = 16; o > 0; o >>= 1) {
        #pragma unroll
        for (int g = 0; g < GG; g++) {
            s0[g] += __shfl_xor_sync(0xffffffffu, s0[g], o);
            s1[g] += __shfl_xor_sync(0xffffffffu, s1[g], o);
        }
    }

    float r0 = 0.f, r1 = 0.f;
    #pragma unroll
    for (int g = 0; g < GG; g++)
        if (lane == g) { r0 = s0[g]; r1 = s1[g]; }
    if (lane < GG) {
        float* sg = score + ((size_t)b * GG + lane) * PP;
        sg[p0] = r0 + ba;
        if (v1) sg[p1] = r1 + ba;
    }
}

// ---------------------------------------------------------------------------
// K3b (fused): 640 threads = 20 warps; warp w owns g = w. Scores staged via
// cp.async (committed first) so softmax starts while the tile still loads.
// grid (8 a-chunks, B); alpha writes distributed.
// ---------------------------------------------------------------------------
__global__ __launch_bounds__(640) void k_soft_wsum(
    const float* __restrict__ score, float* __restrict__ out_alpha,
    float* __restrict__ out_res)
{
    __shared__ __align__(16) float sal[GG * PP];      // 15.7KB
    __shared__ __align__(16) __half2 tile[PP * 32];   // 25KB: [p][32 half2]

    const int b = blockIdx.y, a0 = blockIdx.x * 64;
    const int t = threadIdx.x, warp = t >> 5, lane = t & 31;

    // group 1: scores (980 16B chunks; contiguous) -- committed FIRST
    {
        const char* src = (const char*)(score + (size_t)b * GG * PP);
        const uint32_t sb = smem_u32(sal);
        #pragma unroll
        for (int i = 0; i < 2; i++) {
            int u = t + i * 640;
            if (u < (GG * PP) / 4) cp16(sb + u * 16, src + u * 16);
        }
        asm volatile("cp.async.commit_group;");
    }
    // group 2: att_enc tile (1568 16B chunks)
    {
        const char* src = (const char*)(g_att_encH + (size_t)b * PP * AA + a0);
        const uint32_t tb = smem_u32(tile);
        #pragma unroll
        for (int i = 0; i < 3; i++) {
            int u = t + i * 640;
            if (u < PP * 8) {
                int p = u >> 3, c = u & 7;
                cp16(tb + u * 16, src + (size_t)p * AA * 2 + c * 16);
            }
        }
        asm volatile("cp.async.commit_group;");
    }

    asm volatile("cp.async.wait_group 1;");   // scores ready; tile in flight
    __syncthreads();

    // softmax: warp w handles g = w (single round, 20 warps)
    {
        float* row = sal + warp * PP;
        float m = -1e30f;
        for (int p = lane; p < PP; p += 32) m = fmaxf(m, row[p]);
        #pragma unroll
        for (int o = 16; o > 0; o >>= 1)
            m = fmaxf(m, __shfl_xor_sync(0xffffffffu, m, o));
        float sum = 0.f;
        for (int p = lane; p < PP; p += 32) {
            float ex = __expf(row[p] - m);
            row[p] = ex;
            sum += ex;
        }
        #pragma unroll
        for (int o = 16; o > 0; o >>= 1)
            sum += __shfl_xor_sync(0xffffffffu, sum, o);
        const float inv = 1.f / sum;
        for (int p = lane; p < PP; p += 32) row[p] *= inv;
    }
    asm volatile("cp.async.wait_group 0;");   // tile ready
    __syncthreads();

    // alpha writes distributed across the 8 blocks
    {
        const int gl = (blockIdx.x * GG) / 8;
        const int gh = ((blockIdx.x + 1) * GG) / 8;
        float* ao = out_alpha + (size_t)b * GG * PP;
        for (int i = t; i < (gh - gl) * PP; i += 640)
            ao[gl * PP + i] = sal[gl * PP + i];
    }

    // wsum: warp = g, lane = half2 column; alpha via broadcast float4 loads
    const int g = warp;
    float2 acc = make_float2(0.f, 0.f);
    const float4* s4 = (const float4*)(sal + g * PP);   // 49 float4

    #pragma unroll 7
    for (int p4 = 0; p4 < PP / 4; p4++) {
        float4 A = s4[p4];                              // broadcast
        float2 v0 = __half22float2(tile[(4 * p4 + 0) * 32 + lane]);
        float2 v1 = __half22float2(tile[(4 * p4 + 1) * 32 + lane]);
        float2 v2 = __half22float2(tile[(4 * p4 + 2) * 32 + lane]);
        float2 v3 = __half22float2(tile[(4 * p4 + 3) * 32 + lane]);
        acc.x = fmaf(A.x, v0.x, acc.x); acc.y = fmaf(A.x, v0.y, acc.y);
        acc.x = fmaf(A.y, v1.x, acc.x); acc.y = fmaf(A.y, v1.y, acc.y);
        acc.x = fmaf(A.z, v2.x, acc.x); acc.y = fmaf(A.z, v2.y, acc.y);
        acc.x = fmaf(A.w, v3.x, acc.x); acc.y = fmaf(A.w, v3.y, acc.y);
    }
    *(float2*)&out_res[((size_t)b * GG + g) * AA + a0 + 2 * lane] = acc;
}

// ---------------------------------------------------------------------------
extern "C" void kernel_launch(void* const* d_in, const int* in_sizes, int n_in,
                              void* d_out, int out_size)
{
    const float* enc     = (const float*)d_in[0];
    const float* dec     = (const float*)d_in[1];
    const float* W_enc   = (const float*)d_in[2];
    const float* b_enc   = (const float*)d_in[3];
    const float* W_dec   = (const float*)d_in[4];
    const float* b_dec   = (const float*)d_in[5];
    const float* w_alpha = (const float*)d_in[6];
    const float* b_alpha = (const float*)d_in[7];

    float* out = (float*)d_out;
    float* out_res   = out;                        // (B,G,A)
    float* out_alpha = out + (size_t)M2 * AA;      // (B,G,P)

    __half *A1, *B1, *A2, *B2, *attH;
    float *att_dec, *score;
    cudaGetSymbolAddress((void**)&A1, g_A1);
    cudaGetSymbolAddress((void**)&B1, g_B1);
    cudaGetSymbolAddress((void**)&A2, g_A2);
    cudaGetSymbolAddress((void**)&B2, g_B2);
    cudaGetSymbolAddress((void**)&attH, g_att_encH);
    cudaGetSymbolAddress((void**)&att_dec, g_att_dec);
    cudaGetSymbolAddress((void**)&score, g_score);

    cudaFuncSetAttribute(k_gemm_all, cudaFuncAttributeMaxDynamicSharedMemorySize, SMEM_GEMM);

    // 1: all prep (independent blocks)
    k_prep_all<<<3680, 256>>>(enc, dec, W_enc, W_dec, A1, B1, A2, B2);

    // 2: both GEMMs, 216 CTAs all resident (2/SM)
    k_gemm_all<<<G1_BLOCKS + G2_BLOCKS, 256, SMEM_GEMM>>>(
        A1, B1, A2, B2, b_enc, b_dec, attH, att_dec);

    // 3: scores (packed-butterfly reduction)
    k_score<<<dim3(13, BATCH), 256>>>(w_alpha, b_alpha, score);

    // 4: softmax + weighted sum (cp.async sal + tile, overlapped)
    k_soft_wsum<<<dim3(8, BATCH), 640>>>(score, out_alpha, out_res);
}

// round 17
// speedup vs baseline: 1.0741x; 1.0741x over previous
#include <cuda_runtime.h>
#include <cuda_fp16.h>
#include <cstdint>

// Problem constants
#define BATCH 32
#define CC 2048       // channels (K of GEMM1)
#define PP 196        // H*W
#define GG 20         // decoder steps
#define DD 1024       // decode size (K of GEMM2)
#define AA 512        // att size (N of both GEMMs)

#define M1 (BATCH*PP)      // 6272 = 49*128
#define MT1 49
#define M2 (BATCH*GG)      // 640 = 5*128
#define MT2 5
#define KSEC1 64           // 2048/32 k-chunks (GEMM1)
#define KSEC2 32           // 1024/32 (GEMM2)

// GEMM tiling: CTA 128x64, 4 warps (2x2), warp 64x32, chunk K=32.
#define STAGES 4
#define CHUNK_A 8192              // 128 x 32 x 2B
#define CHUNK_B 4096              // 64 x 32 x 2B
#define SROW 80                   // smem row pitch (64B data + 16B pad)
#define SUBT_A (128*SROW)         // 10240
#define SUBT_B (64*SROW)          // 5120
#define STAGE_BYTES (SUBT_A + SUBT_B)    // 15360
#define SMEM_GEMM (STAGES*STAGE_BYTES)   // 61440

#define G1_BLOCKS (8*MT1)         // 392
#define G2_BLOCKS (8*MT2)         // 40

// ---------------------------------------------------------------------------
// Scratch
// ---------------------------------------------------------------------------
__device__ __align__(16) __half g_A1[MT1 * KSEC1 * 4096];   // 25.7 MB
__device__ __align__(16) __half g_B1[8   * KSEC1 * 2048];   // 2.1 MB
__device__ __align__(16) __half g_A2[MT2 * KSEC2 * 4096];
__device__ __align__(16) __half g_B2[8   * KSEC2 * 2048];
__device__ __align__(16) __half g_att_encH[M1*AA];   // (B,P,A) fp16, 6.4MB
__device__ float g_att_dec[M2*AA];                   // (B,G,A) fp32
__device__ float g_score[M2*PP];                     // (B,G,P)

// ---------------------------------------------------------------------------
__device__ __forceinline__ uint32_t smem_u32(const void* p) {
    uint32_t a;
    asm("{ .reg .u64 t; cvta.to.shared.u64 t, %1; cvt.u32.u64 %0, t; }" : "=r"(a) : "l"(p));
    return a;
}
__device__ __forceinline__ void cp16(uint32_t saddr, const void* gaddr) {
    asm volatile("cp.async.cg.shared.global [%0], [%1], 16;" :: "r"(saddr), "l"(gaddr));
}
__device__ __forceinline__ void ldm_x4(uint32_t* r, uint32_t addr) {
    asm volatile("ldmatrix.sync.aligned.m8n8.x4.shared.b16 {%0,%1,%2,%3}, [%4];"
        : "=r"(r[0]), "=r"(r[1]), "=r"(r[2]), "=r"(r[3]) : "r"(addr));
}
__device__ __forceinline__ void mma16816(float* c, const uint32_t* a, uint32_t b0, uint32_t b1) {
    asm volatile("mma.sync.aligned.m16n8k16.row.col.f32.f16.f16.f32 "
        "{%0,%1,%2,%3}, {%4,%5,%6,%7}, {%8,%9}, {%0,%1,%2,%3};"
        : "+f"(c[0]), "+f"(c[1]), "+f"(c[2]), "+f"(c[3])
        : "r"(a[0]), "r"(a[1]), "r"(a[2]), "r"(a[3]), "r"(b0), "r"(b1));
}

// ---------------------------------------------------------------------------
// Merged prep kernel.
// ---------------------------------------------------------------------------
__device__ __forceinline__ void prep_B_body(
    const float* __restrict__ W, __half* __restrict__ Bst, int kSec,
    int kc, int nb, int t, float* sm)
{
    #pragma unroll
    for (int i = 0; i < 16; i++) {
        int idx = t + i * 256;
        int kl = idx >> 7, nl = idx & 127;
        sm[kl * 129 + nl] = W[(size_t)(kc * 32 + kl) * AA + nb * 128 + nl];
    }
    __syncthreads();
    #pragma unroll
    for (int i = 0; i < 8; i++) {
        int e2 = t + i * 256;
        int row = e2 >> 4, cp = e2 & 15;
        float x0 = sm[(2*cp)   * 129 + row];
        float x1 = sm[(2*cp+1) * 129 + row];
        int nt = nb * 2 + (row >> 6);
        int rl = row & 63;
        __half2* dst = (__half2*)(Bst + ((size_t)nt * kSec + kc) * 2048);
        dst[rl * 16 + cp] = __halves2half2(__float2half_rn(x0), __float2half_rn(x1));
    }
}

__global__ __launch_bounds__(256) void k_prep_all(
    const float* __restrict__ enc, const float* __restrict__ dec,
    const float* __restrict__ W_enc, const float* __restrict__ W_dec,
    __half* __restrict__ A1, __half* __restrict__ B1,
    __half* __restrict__ A2, __half* __restrict__ B2)
{
    __shared__ float sm[32 * 129];
    const int id = blockIdx.x;
    const int t = threadIdx.x;

    if (id < 3136) {
        const int kc = id & 63, mt = id >> 6;
        #pragma unroll
        for (int i = 0; i < 16; i++) {
            int idx = t + i * 256;            // 4096 = 32c x 128m
            int cl = idx >> 7, ml = idx & 127;
            int m = mt * 128 + ml;
            int b = m / PP, p = m - b * PP;
            sm[cl * 129 + ml] = enc[((size_t)b * CC + (kc * 32 + cl)) * PP + p];
        }
        __syncthreads();
        __half2* hiC = (__half2*)(A1 + ((size_t)mt * KSEC1 + kc) * 4096);
        #pragma unroll
        for (int i = 0; i < 8; i++) {
            int e2 = t + i * 256;             // 2048 half2 = 128r x 16
            int row = e2 >> 4, cp = e2 & 15;
            float x0 = sm[(2*cp)   * 129 + row];
            float x1 = sm[(2*cp+1) * 129 + row];
            hiC[row * 16 + cp] = __halves2half2(__float2half_rn(x0), __float2half_rn(x1));
        }
    } else if (id < 3392) {
        int j = id - 3136;
        prep_B_body(W_enc, B1, KSEC1, j & 63, j >> 6, t, sm);
    } else if (id < 3520) {
        int j = id - 3392;
        prep_B_body(W_dec, B2, KSEC2, j & 31, j >> 5, t, sm);
    } else {
        int j = id - 3520;
        int kc = j & 31, mt = j >> 5;
        __half2* hiC = (__half2*)(A2 + ((size_t)mt * KSEC2 + kc) * 4096);
        #pragma unroll
        for (int i = 0; i < 8; i++) {
            int e2 = t + i * 256;
            int row = e2 >> 4, cp = e2 & 15;
            const float* src = dec + (size_t)(mt * 128 + row) * DD + kc * 32 + 2*cp;
            hiC[row * 16 + cp] = __halves2half2(__float2half_rn(src[0]), __float2half_rn(src[1]));
        }
    }
}

// ---------------------------------------------------------------------------
// Merged fp16 mma.sync GEMM (R12-exact): CTA 128x64, 128 threads, 4 stages,
// prefetch issued AFTER compute. id < 392: GEMM1 -> fp16; else GEMM2 -> fp32.
// ---------------------------------------------------------------------------
__global__ __launch_bounds__(128, 3) void k_gemm_all(
    const __half* __restrict__ A1g, const __half* __restrict__ B1g,
    const __half* __restrict__ A2g, const __half* __restrict__ B2g,
    const float* __restrict__ b_enc, const float* __restrict__ b_dec,
    __half* __restrict__ out1, float* __restrict__ out2)
{
    extern __shared__ __align__(16) char smem[];
    const int id = blockIdx.x;
    const int t = threadIdx.x;
    const int lane = t & 31, wid = t >> 5;
    const int wm = wid >> 1, wn = wid & 1;        // warp tile (wm*64, wn*32)

    const bool g1 = (id < G1_BLOCKS);
    const int j  = g1 ? id : id - G1_BLOCKS;
    const int mt = j >> 3, nt = j & 7;
    const int kSec = g1 ? KSEC1 : KSEC2;
    const __half* Ast = g1 ? A1g : A2g;
    const __half* Bst = g1 ? B1g : B2g;
    const float* bias = g1 ? b_enc : b_dec;

    const char* Abase = (const char*)(Ast + (size_t)mt * kSec * 4096);
    const char* Bbase = (const char*)(Bst + (size_t)nt * kSec * 2048);
    const uint32_t smem_base = smem_u32(smem);

    auto issue = [&](int kc) {
        const int s = kc % STAGES;
        const char* ga = Abase + (size_t)kc * CHUNK_A;
        const char* gb = Bbase + (size_t)kc * CHUNK_B;
        const uint32_t st = smem_base + s * STAGE_BYTES;
        #pragma unroll
        for (int jj = 0; jj < 4; jj++) {   // A: 512 16B-chunks
            int u = t + jj * 128;
            cp16(st + (u >> 2) * SROW + (u & 3) * 16, ga + u * 16);
        }
        #pragma unroll
        for (int jj = 0; jj < 2; jj++) {   // B: 256 16B-chunks
            int u = t + jj * 128;
            cp16(st + SUBT_A + (u >> 2) * SROW + (u & 3) * 16, gb + u * 16);
        }
        asm volatile("cp.async.commit_group;");
    };

    issue(0); issue(1); issue(2);

    float c[4][4][4];
    #pragma unroll
    for (int mi = 0; mi < 4; mi++)
        #pragma unroll
        for (int nj = 0; nj < 4; nj++)
            #pragma unroll
            for (int q = 0; q < 4; q++) c[mi][nj][q] = 0.f;

    for (int kc = 0; kc < kSec; kc++) {
        asm volatile("cp.async.wait_group 2;");
        __syncthreads();
        const int s = kc % STAGES;
        const uint32_t st = smem_base + s * STAGE_BYTES;
        const uint32_t aB = st + (wm * 64 + (lane & 15)) * SROW + (lane >> 4) * 16;
        const uint32_t bB = st + SUBT_A + (wn * 32 + (lane & 15)) * SROW + (lane >> 4) * 16;
        #pragma unroll
        for (int ks = 0; ks < 2; ks++) {
            const uint32_t ko = ks * 32;
            uint32_t a[4][4], bh[2][4];
            #pragma unroll
            for (int mi = 0; mi < 4; mi++) ldm_x4(a[mi], aB + mi * 16 * SROW + ko);
            #pragma unroll
            for (int nj = 0; nj < 2; nj++) ldm_x4(bh[nj], bB + nj * 16 * SROW + ko);
            #pragma unroll
            for (int mi = 0; mi < 4; mi++)
                #pragma unroll
                for (int n8 = 0; n8 < 4; n8++) {
                    const int nj = n8 >> 1, hl = n8 & 1;
                    mma16816(c[mi][n8], a[mi], bh[nj][hl], bh[nj][hl + 2]);
                }
        }
        if (kc + 3 < kSec) issue(kc + 3);
        else asm volatile("cp.async.commit_group;");
    }

    // epilogue
    const int r0b = mt * 128 + wm * 64 + (lane >> 2);
    const int ncb = nt * 64 + wn * 32 + (lane & 3) * 2;
    #pragma unroll
    for (int mi = 0; mi < 4; mi++) {
        #pragma unroll
        for (int n8 = 0; n8 < 4; n8++) {
            const int n = ncb + n8 * 8;
            const float b0 = bias[n], b1 = bias[n + 1];
            const size_t o0 = (size_t)(r0b + mi * 16) * AA + n;
            if (g1) {
                *(__half2*)(out1 + o0) =
                    __floats2half2_rn(c[mi][n8][0] + b0, c[mi][n8][1] + b1);
                *(__half2*)(out1 + o0 + 8 * AA) =
                    __floats2half2_rn(c[mi][n8][2] + b0, c[mi][n8][3] + b1);
            } else {
                float2 v0 = { c[mi][n8][0] + b0, c[mi][n8][1] + b1 };
                float2 v1 = { c[mi][n8][2] + b0, c[mi][n8][3] + b1 };
                *(float2*)(out2 + o0) = v0;
                *(float2*)(out2 + o0 + 8 * AA) = v1;
            }
        }
    }
}

// ---------------------------------------------------------------------------
// K3a: scores. Warp = 2 pixels, s[20] accumulators per lane, ONE packed
// butterfly at the end. grid (13, B).
// ---------------------------------------------------------------------------
__global__ __launch_bounds__(256) void k_score(
    const float* __restrict__ w_alpha, const float* __restrict__ b_alpha,
    float* __restrict__ score)
{
    __shared__ __half2 sdec[GG * 256];   // [g][256 half2] 20KB
    __shared__ float sw_[AA];            // 2KB
    const int b = blockIdx.y;
    const int t = threadIdx.x, warp = t >> 5, lane = t & 31;

    const float* dptr = g_att_dec + (size_t)b * GG * AA;
    for (int i = t; i < GG * 256; i += 256) {
        int g = i >> 8, c = i & 255;
        float2 d2 = *(const float2*)&dptr[g * AA + 2 * c];
        sdec[i] = __floats2half2_rn(d2.x, d2.y);
    }
    for (int i = t; i < AA; i += 256) sw_[i] = w_alpha[i];
    __syncthreads();

    const int p0 = blockIdx.x * 16 + warp * 2;
    const int p1 = p0 + 1;
    if (p0 >= PP) return;
    const bool v1 = (p1 < PP);
    const int p1c = v1 ? p1 : p0;
    const float ba = b_alpha[0];
    const __half2* ep0 = (const __half2*)(g_att_encH + ((size_t)b * PP + p0) * AA);
    const __half2* ep1 = (const __half2*)(g_att_encH + ((size_t)b * PP + p1c) * AA);

    float s0[GG], s1[GG];
    #pragma unroll
    for (int g = 0; g < GG; g++) { s0[g] = 0.f; s1[g] = 0.f; }

    #pragma unroll
    for (int i = 0; i < 8; i++) {
        float2 e0 = __half22float2(ep0[lane + 32 * i]);
        float2 e1 = __half22float2(ep1[lane + 32 * i]);
        float2 w  = *(const float2*)&sw_[2 * (lane + 32 * i)];
        #pragma unroll
        for (int g = 0; g < GG; g++) {
            float2 d = __half22float2(sdec[g * 256 + lane + 32 * i]);
            s0[g] = fmaf(fmaxf(e0.x + d.x, 0.f), w.x, s0[g]);
            s0[g] = fmaf(fmaxf(e0.y + d.y, 0.f), w.y, s0[g]);
            s1[g] = fmaf(fmaxf(e1.x + d.x, 0.f), w.x, s1[g]);
            s1[g] = fmaf(fmaxf(e1.y + d.y, 0.f), w.y, s1[g]);
        }
    }

    #pragma unroll
    for (int o = 16; o > 0; o >>= 1) {
        #pragma unroll
        for (int g = 0; g < GG; g++) {
            s0[g] += __shfl_xor_sync(0xffffffffu, s0[g], o);
            s1[g] += __shfl_xor_sync(0xffffffffu, s1[g], o);
        }
    }

    float r0 = 0.f, r1 = 0.f;
    #pragma unroll
    for (int g = 0; g < GG; g++)
        if (lane == g) { r0 = s0[g]; r1 = s1[g]; }
    if (lane < GG) {
        float* sg = score + ((size_t)b * GG + lane) * PP;
        sg[p0] = r0 + ba;
        if (v1) sg[p1] = r1 + ba;
    }
}

// ---------------------------------------------------------------------------
// K3b (fused, R15-exact): 640 threads = 20 warps; warp w owns g = w.
// Scores + tile staged via cp.async in two groups; softmax overlaps tile load.
// grid (8 a-chunks, B); alpha writes distributed.
// ---------------------------------------------------------------------------
__global__ __launch_bounds__(640) void k_soft_wsum(
    const float* __restrict__ score, float* __restrict__ out_alpha,
    float* __restrict__ out_res)
{
    __shared__ __align__(16) float sal[GG * PP];      // 15.7KB
    __shared__ __align__(16) __half2 tile[PP * 32];   // 25KB: [p][32 half2]

    const int b = blockIdx.y, a0 = blockIdx.x * 64;
    const int t = threadIdx.x, warp = t >> 5, lane = t & 31;

    // group 1: scores (980 16B chunks; contiguous) -- committed FIRST
    {
        const char* src = (const char*)(score + (size_t)b * GG * PP);
        const uint32_t sb = smem_u32(sal);
        #pragma unroll
        for (int i = 0; i < 2; i++) {
            int u = t + i * 640;
            if (u < (GG * PP) / 4) cp16(sb + u * 16, src + u * 16);
        }
        asm volatile("cp.async.commit_group;");
    }
    // group 2: att_enc tile (1568 16B chunks)
    {
        const char* src = (const char*)(g_att_encH + (size_t)b * PP * AA + a0);
        const uint32_t tb = smem_u32(tile);
        #pragma unroll
        for (int i = 0; i < 3; i++) {
            int u = t + i * 640;
            if (u < PP * 8) {
                int p = u >> 3, c = u & 7;
                cp16(tb + u * 16, src + (size_t)p * AA * 2 + c * 16);
            }
        }
        asm volatile("cp.async.commit_group;");
    }

    asm volatile("cp.async.wait_group 1;");   // scores ready; tile in flight
    __syncthreads();

    // softmax: warp w handles g = w (single round, 20 warps)
    {
        float* row = sal + warp * PP;
        float m = -1e30f;
        for (int p = lane; p < PP; p += 32) m = fmaxf(m, row[p]);
        #pragma unroll
        for (int o = 16; o > 0; o >>= 1)
            m = fmaxf(m, __shfl_xor_sync(0xffffffffu, m, o));
        float sum = 0.f;
        for (int p = lane; p < PP; p += 32) {
            float ex = __expf(row[p] - m);
            row[p] = ex;
            sum += ex;
        }
        #pragma unroll
        for (int o = 16; o > 0; o >>= 1)
            sum += __shfl_xor_sync(0xffffffffu, sum, o);
        const float inv = 1.f / sum;
        for (int p = lane; p < PP; p += 32) row[p] *= inv;
    }
    asm volatile("cp.async.wait_group 0;");   // tile ready
    __syncthreads();

    // alpha writes distributed across the 8 blocks
    {
        const int gl = (blockIdx.x * GG) / 8;
        const int gh = ((blockIdx.x + 1) * GG) / 8;
        float* ao = out_alpha + (size_t)b * GG * PP;
        for (int i = t; i < (gh - gl) * PP; i += 640)
            ao[gl * PP + i] = sal[gl * PP + i];
    }

    // wsum: warp = g, lane = half2 column; alpha via broadcast float4 loads
    const int g = warp;
    float2 acc = make_float2(0.f, 0.f);
    const float4* s4 = (const float4*)(sal + g * PP);   // 49 float4

    #pragma unroll 7
    for (int p4 = 0; p4 < PP / 4; p4++) {
        float4 A = s4[p4];                              // broadcast
        float2 v0 = __half22float2(tile[(4 * p4 + 0) * 32 + lane]);
        float2 v1 = __half22float2(tile[(4 * p4 + 1) * 32 + lane]);
        float2 v2 = __half22float2(tile[(4 * p4 + 2) * 32 + lane]);
        float2 v3 = __half22float2(tile[(4 * p4 + 3) * 32 + lane]);
        acc.x = fmaf(A.x, v0.x, acc.x); acc.y = fmaf(A.x, v0.y, acc.y);
        acc.x = fmaf(A.y, v1.x, acc.x); acc.y = fmaf(A.y, v1.y, acc.y);
        acc.x = fmaf(A.z, v2.x, acc.x); acc.y = fmaf(A.z, v2.y, acc.y);
        acc.x = fmaf(A.w, v3.x, acc.x); acc.y = fmaf(A.w, v3.y, acc.y);
    }
    *(float2*)&out_res[((size_t)b * GG + g) * AA + a0 + 2 * lane] = acc;
}

// ---------------------------------------------------------------------------
extern "C" void kernel_launch(void* const* d_in, const int* in_sizes, int n_in,
                              void* d_out, int out_size)
{
    const float* enc     = (const float*)d_in[0];
    const float* dec     = (const float*)d_in[1];
    const float* W_enc   = (const float*)d_in[2];
    const float* b_enc   = (const float*)d_in[3];
    const float* W_dec   = (const float*)d_in[4];
    const float* b_dec   = (const float*)d_in[5];
    const float* w_alpha = (const float*)d_in[6];
    const float* b_alpha = (const float*)d_in[7];

    float* out = (float*)d_out;
    float* out_res   = out;                        // (B,G,A)
    float* out_alpha = out + (size_t)M2 * AA;      // (B,G,P)

    __half *A1, *B1, *A2, *B2, *attH;
    float *att_dec, *score;
    cudaGetSymbolAddress((void**)&A1, g_A1);
    cudaGetSymbolAddress((void**)&B1, g_B1);
    cudaGetSymbolAddress((void**)&A2, g_A2);
    cudaGetSymbolAddress((void**)&B2, g_B2);
    cudaGetSymbolAddress((void**)&attH, g_att_encH);
    cudaGetSymbolAddress((void**)&att_dec, g_att_dec);
    cudaGetSymbolAddress((void**)&score, g_score);

    cudaFuncSetAttribute(k_gemm_all, cudaFuncAttributeMaxDynamicSharedMemorySize, SMEM_GEMM);

    // 1: all prep (independent blocks)
    k_prep_all<<<3680, 256>>>(enc, dec, W_enc, W_dec, A1, B1, A2, B2);

    // 2: both GEMMs in one wave (432 CTAs @ 3/SM)
    k_gemm_all<<<G1_BLOCKS + G2_BLOCKS, 128, SMEM_GEMM>>>(
        A1, B1, A2, B2, b_enc, b_dec, attH, att_dec);

    // 3: scores (packed-butterfly reduction)
    k_score<<<dim3(13, BATCH), 256>>>(w_alpha, b_alpha, score);

    // 4: softmax + weighted sum (cp.async sal + tile, overlapped)
    k_soft_wsum<<<dim3(8, BATCH), 640>>>(score, out_alpha, out_res);
}